// round 10
// baseline (speedup 1.0000x reference)
#include <cuda_runtime.h>
#include <math.h>

// ---------------------------------------------------------------------------
// DilatedSparseRnnStack — R10: paired CTAs, 16 rows per group, gate-split.
// Rank0 owns cols 0-127 (the `out` half), rank1 owns cols 128-255 (the `H`
// half). Each CTA reads only HALF the weights -> chip weight traffic halves
// (806 -> 403 MB/step), dropping the LTS floor below the FFMA2 floor.
// Per-thread: 2 gates (LDG.64 gate-pair) x 8 row-pairs = 16 f32x2 accums.
// Cross-CTA: rank0 publishes `out` via L2 buffer, rank1 publishes H via the
// global circular buffer; per-layer release/acquire flags keep lockstep.
// ---------------------------------------------------------------------------

namespace {
constexpr int T_STEPS = 256;
constexpr int BATCH   = 1024;
constexpr int IN_F    = 64;
constexpr int HSZ     = 128;
constexpr int OSZ     = 128;
constexpr int OUT_F   = 8;
constexpr int RPG     = 16;              // rows per group
constexpr int NGRP    = BATCH / RPG;     // 64 groups
constexpr int NCTA    = NGRP * 2;        // 128 CTAs
constexpr int NTHR    = 512;
constexpr int KTOT    = 320 + 384 + 448 + 384;  // 1536

// dynamic SMEM layout (bytes)
constexpr int SM_XH    = 0;         // 448*16*4 = 28672
constexpr int SM_RED   = 28672;     // 4g*8p*2q*128j*8B = 65536
constexpr int SM_OUT   = 94208;     // 128*16*4 = 8192
constexpr int SM_WOUT  = 102400;    // 8*132*4 = 4224 -> pad 4352
constexpr int SM_BIAS  = 106752;    // 4*128*16 = 8192
constexpr int SM_TOTAL = 114944;
constexpr int WOUT_S   = 132;       // padded row stride (bank-conflict free)
}

// Weights, transposed + gate-pair interleaved:
// element offset = LOFF + ((k*2 + gp)*256 + jc)*2 + gl   (gp,gl in 0..1)
__device__ float g_WT2[(size_t)KTOT * 1024];

// Dilation buffers, group-local layout (slot offsets {0,1,4,10}, sizes {1,3,6,12}):
//   C: [slot 22][group 64][jc 256][r 16]   H: [slot 22][group 64][jh 128][r 16]
__device__ float4 g_bufC4[(size_t)22 * 64 * 256 * 4];
__device__ float4 g_bufH4[(size_t)22 * 64 * 128 * 4];

// out exchange buffer: [layer 0..2][group][jh*4 + o]
__device__ float4 g_out4[3][64][512];
// lockstep flags (single writer each; accessed only via acquire/release asm)
__device__ int g_flagO[64][4];
__device__ int g_flagH[64][4];

__device__ __forceinline__ float sigf(float v) {
    return 1.0f / (1.0f + __expf(-v));
}
__device__ __forceinline__ void ffma2(unsigned long long& d,
                                      unsigned long long a,
                                      unsigned long long b) {
    asm("fma.rn.f32x2 %0, %1, %2, %0;" : "+l"(d) : "l"(a), "l"(b));
}
__device__ __forceinline__ void fadd2(unsigned long long& d,
                                      unsigned long long a) {
    asm("add.rn.f32x2 %0, %0, %1;" : "+l"(d) : "l"(a));
}
__device__ __forceinline__ unsigned long long dup2(float w) {
    unsigned long long r;
    asm("mov.b64 %0, {%1, %1};" : "=l"(r) : "f"(w));
    return r;
}
__device__ __forceinline__ float2 u2f2(unsigned long long v) {
    float2 f;
    asm("mov.b64 {%0, %1}, %2;" : "=f"(f.x), "=f"(f.y) : "l"(v));
    return f;
}
__device__ __forceinline__ void wait_flag(int* f, int needed) {
    int v;
    do {
        asm volatile("ld.acquire.gpu.b32 %0, [%1];" : "=r"(v) : "l"(f));
    } while (!(v >= needed && v < needed + 64));
}
__device__ __forceinline__ void set_flag(int* f, int v) {
    asm volatile("st.release.gpu.b32 [%0], %1;" :: "l"(f), "r"(v) : "memory");
}

// ---------------------------------------------------------------------------
// Prep: transpose + gate-pair interleave weights.
// ---------------------------------------------------------------------------
__global__ void prep_kernel(const float* __restrict__ W0,
                            const float* __restrict__ W1,
                            const float* __restrict__ W2,
                            const float* __restrict__ W3)
{
    const int li = blockIdx.y;
    const float* W;
    int K, off;
    if (li == 0)      { W = W0; K = 320; off = 0; }
    else if (li == 1) { W = W1; K = 384; off = 320 * 1024; }
    else if (li == 2) { W = W2; K = 448; off = 704 * 1024; }
    else              { W = W3; K = 384; off = 1152 * 1024; }

    int idx = blockIdx.x * 256 + threadIdx.x;
    if (idx < 1024 * K) {
        int row = idx / K;           // g*256 + j
        int k   = idx - row * K;
        int g = row >> 8, j = row & 255;
        g_WT2[(size_t)off + ((size_t)(k * 2 + (g >> 1)) * 256 + j) * 2 + (g & 1)]
            = W[idx];
    }
}

// ---------------------------------------------------------------------------
// One layer step.
// thread: jl = tid&127 (col within CTA), gp = (tid>>7)&1 (gate pair),
//         q = tid>>8 (k-half), o = tid>>7 (epilogue owner, rows 4o..4o+3)
// ---------------------------------------------------------------------------
template <int K, int DIL, int LOFF, int LI, int WTOFF>
__device__ __forceinline__ void do_layer(
    int t, int tid, int group, int rank, int cbase,
    const float* __restrict__ xt,
    char* __restrict__ smem)
{
    const int prevSlot = LOFF + (t - 1 + DIL) % DIL;
    const int curSlot  = LOFF + (t % DIL);
    const int jl = tid & 127;
    const int gp = (tid >> 7) & 1;
    const int q  = tid >> 8;
    const int o  = tid >> 7;           // 0..3
    const int jc = cbase + jl;

    float* s_xhf = reinterpret_cast<float*>(smem + SM_XH);
    unsigned long long* s_red =
        reinterpret_cast<unsigned long long*>(smem + SM_RED);
    float4* s_out4 = reinterpret_cast<float4*>(smem + SM_OUT);

    __syncthreads();  // sync A: prev layer fully consumed + published

    // ---- lockstep waits ----
    if (tid == 0) {
        if (rank == 0) {
            if (t >= 1) wait_flag(&g_flagH[group][LI], (t - 1) * 4 + LI + 1);
        } else {
            if (LI >= 1) wait_flag(&g_flagO[group][LI - 1], t * 4 + LI);
        }
    }
    __syncthreads();  // sync A2

    // ---- C-state prefetch: float4 = owned rows 4o..4o+3 of col jc ----
    const size_t cIdx = ((size_t)(curSlot  * 64 + group) * 256 + jc) * 4 + o;
    const size_t pIdx = ((size_t)(prevSlot * 64 + group) * 256 + jc) * 4 + o;
    float4 pC4 = make_float4(0.f, 0.f, 0.f, 0.f);
    float4 dC4 = make_float4(0.f, 0.f, 0.f, 0.f);
    if (t > 0)    pC4 = g_bufC4[pIdx];
    if (t >= DIL) dC4 = g_bufC4[cIdx];

    // ---- build xh: s_xhf[k*16 + r], r = row within group ----
    if (LI > 0) {
        const int jh = tid >> 2, oo = tid & 3;
        float4 v = (rank == 0) ? s_out4[jh * 4 + oo]
                               : g_out4[LI - 1][group][jh * 4 + oo];
        *reinterpret_cast<float4*>(&s_xhf[jh * 16 + oo * 4]) = v;
    }
    if (LI == 0 || LI == 2) {
        constexpr int XOFF = (LI == 0) ? 0 : OSZ;
        if (tid < 256) {
            int k4 = tid >> 4, r = tid & 15;
            float4 v = reinterpret_cast<const float4*>(xt)[r * 16 + k4];
            int b = (XOFF + k4 * 4) * 16 + r;
            s_xhf[b]      = v.x;
            s_xhf[b + 16] = v.y;
            s_xhf[b + 32] = v.z;
            s_xhf[b + 48] = v.w;
        }
    }
    {
        constexpr int HOFF = (LI == 0) ? IN_F : (LI == 2) ? (OSZ + IN_F) : OSZ;
        const int jh = tid >> 2, oo = tid & 3;
        float4 pv = make_float4(0.f, 0.f, 0.f, 0.f);
        float4 dv = pv;
        if (t > 0) {
            pv = g_bufH4[((size_t)(prevSlot * 64 + group) * 128 + jh) * 4 + oo];
            dv = (t >= DIL)
               ? g_bufH4[((size_t)(curSlot * 64 + group) * 128 + jh) * 4 + oo]
               : pv;
        }
        *reinterpret_cast<float4*>(&s_xhf[(HOFF + jh) * 16 + oo * 4])       = pv;
        *reinterpret_cast<float4*>(&s_xhf[(HOFF + HSZ + jh) * 16 + oo * 4]) = dv;
    }

    __syncthreads();  // sync B: xh complete

    // ---- GEMM: 2 gates x 8 row-pairs over this k-half ----
    unsigned long long a0[8], a1[8];
#pragma unroll
    for (int p = 0; p < 8; ++p) { a0[p] = 0ull; a1[p] = 0ull; }

    {
        const char* wp = reinterpret_cast<const char*>(g_WT2)
                       + (size_t)WTOFF * 4
                       + (size_t)(gp * 256 + jc) * 8
                       + (size_t)q * (K / 2) * 4096;
        const char* xp = smem + SM_XH + q * (K / 2) * 64;
        for (int kb = 0; kb < K / 2; kb += 4) {
#pragma unroll
            for (int u = 0; u < 4; ++u) {
                float2 w = *reinterpret_cast<const float2*>(wp + u * 4096);
                unsigned long long w0 = dup2(w.x);
                unsigned long long w1 = dup2(w.y);
                ulonglong2 xA = *reinterpret_cast<const ulonglong2*>(xp + u * 64);
                ulonglong2 xB = *reinterpret_cast<const ulonglong2*>(xp + u * 64 + 16);
                ffma2(a0[0], w0, xA.x); ffma2(a1[0], w1, xA.x);
                ffma2(a0[1], w0, xA.y); ffma2(a1[1], w1, xA.y);
                ffma2(a0[2], w0, xB.x); ffma2(a1[2], w1, xB.x);
                ffma2(a0[3], w0, xB.y); ffma2(a1[3], w1, xB.y);
                ulonglong2 xC = *reinterpret_cast<const ulonglong2*>(xp + u * 64 + 32);
                ulonglong2 xD = *reinterpret_cast<const ulonglong2*>(xp + u * 64 + 48);
                ffma2(a0[4], w0, xC.x); ffma2(a1[4], w1, xC.x);
                ffma2(a0[5], w0, xC.y); ffma2(a1[5], w1, xC.y);
                ffma2(a0[6], w0, xD.x); ffma2(a1[6], w1, xD.x);
                ffma2(a0[7], w0, xD.y); ffma2(a1[7], w1, xD.y);
            }
            wp += 4 * 4096;
            xp += 4 * 64;
        }
    }

    // ---- reduction: write all partials, owner sums its 2 pairs ----
    {
        const int g0 = gp * 2;
#pragma unroll
        for (int p = 0; p < 8; ++p) {
            s_red[((g0 * 8 + p) * 2 + q) * 128 + jl]       = a0[p];
            s_red[(((g0 + 1) * 8 + p) * 2 + q) * 128 + jl] = a1[p];
        }
    }
    __syncthreads();  // sync D: partials visible

    unsigned long long G[4][2];
#pragma unroll
    for (int g = 0; g < 4; ++g) {
#pragma unroll
        for (int i = 0; i < 2; ++i) {
            const int pp = 2 * o + i;
            unsigned long long v0 = s_red[((g * 8 + pp) * 2 + 0) * 128 + jl];
            unsigned long long v1 = s_red[((g * 8 + pp) * 2 + 1) * 128 + jl];
            fadd2(v0, v1);
            G[g][i] = v0;
        }
    }

    // ---- epilogue: owned rows 4o..4o+3 of col jc ----
    const float4 bias =
        reinterpret_cast<const float4*>(smem + SM_BIAS)[LI * 128 + jl];
    const float* pCf = &pC4.x;
    const float* dCf = &dC4.x;
    float nc[4], wh[4];
#pragma unroll
    for (int i = 0; i < 2; ++i) {
        float2 g0 = u2f2(G[0][i]);
        float2 g1 = u2f2(G[1][i]);
        float2 g2 = u2f2(G[2][i]);
        float2 g3 = u2f2(G[3][i]);
#pragma unroll
        for (int s = 0; s < 2; ++s) {
            const int r = 2 * i + s;
            float forget = sigf((s ? g0.y : g0.x) + bias.x + 1.0f);
            float cand   = tanhf((s ? g1.y : g1.x) + bias.y);
            float alpha  = sigf((s ? g2.y : g2.x) + bias.z);
            float og     = sigf((s ? g3.y : g3.x) + bias.w);
            float newC;
            if (t == 0) {
                newC = cand;
            } else {
                float wC = pCf[r];
                if (t >= DIL) {
                    wC = alpha * pCf[r] + (1.0f - alpha) * dCf[r];
                }
                newC = forget * wC + (1.0f - forget) * cand;
            }
            nc[r] = newC;
            wh[r] = og * newC;
        }
    }
    g_bufC4[cIdx] = make_float4(nc[0], nc[1], nc[2], nc[3]);
    float4 w4 = make_float4(wh[0], wh[1], wh[2], wh[3]);
    if (rank == 0) {
        s_out4[jl * 4 + o] = w4;
        if (LI < 3) g_out4[LI][group][jl * 4 + o] = w4;
    } else {
        g_bufH4[((size_t)(curSlot * 64 + group) * 128 + jl) * 4 + o] = w4;
    }

    __syncthreads();  // sync E: all epilogue writes done
    if (tid == 0) {
        __threadfence();
        if (rank == 0) {
            if (LI < 3) set_flag(&g_flagO[group][LI], t * 4 + LI + 1);
        } else {
            set_flag(&g_flagH[group][LI], t * 4 + LI + 1);
        }
    }
}

__global__ __launch_bounds__(NTHR, 1) void rnn_stack_kernel(
    const float* __restrict__ x,
    const float* __restrict__ b0, const float* __restrict__ b1,
    const float* __restrict__ b2, const float* __restrict__ b3,
    const float* __restrict__ Wout, const float* __restrict__ bout,
    float* __restrict__ out)
{
    extern __shared__ char smem[];
    float* s_out  = reinterpret_cast<float*>(smem + SM_OUT);
    float* s_wout = reinterpret_cast<float*>(smem + SM_WOUT);

    const int tid   = threadIdx.x;
    const int group = blockIdx.x >> 1;
    const int rank  = blockIdx.x & 1;
    const int cbase = rank * 128;
    const int row0  = group * RPG;

    // reset own flags (consumers reject pre-reset stale values via window)
    if (tid == 0) {
#pragma unroll
        for (int L = 0; L < 4; ++L) {
            if (rank == 0) g_flagO[group][L] = 0;
            else           g_flagH[group][L] = 0;
        }
        __threadfence();
    }

    // Wout into padded smem rows
    if (tid < 256) {
        int oo = tid >> 5, c4 = tid & 31;
        *reinterpret_cast<float4*>(&s_wout[oo * WOUT_S + c4 * 4]) =
            reinterpret_cast<const float4*>(Wout)[oo * 32 + c4];
    }
    // bias table: [layer 4][jl 128] float4 of this CTA's cols
    {
        int L = tid >> 7, jl = tid & 127;
        int jc = cbase + jl;
        const float* bp = (L == 0) ? b0 : (L == 1) ? b1 : (L == 2) ? b2 : b3;
        reinterpret_cast<float4*>(smem + SM_BIAS)[L * 128 + jl] =
            make_float4(bp[jc], bp[256 + jc], bp[512 + jc], bp[768 + jc]);
    }

    // projection mapping (rank0): tid = r*32 + o*4 + seg
    const int p_seg = tid & 3;
    const int p_o   = (tid >> 2) & 7;
    const int p_r   = tid >> 5;
    const float bo  = bout[p_o];

    for (int t = 0; t < T_STEPS; ++t) {
        const float* xt = x + ((size_t)t * BATCH + row0) * IN_F;

        do_layer<320,  1,  0, 0, 0>          (t, tid, group, rank, cbase, xt, smem);
        do_layer<384,  3,  1, 1, 320 * 1024> (t, tid, group, rank, cbase, xt, smem);
        do_layer<448,  6,  4, 2, 704 * 1024> (t, tid, group, rank, cbase, xt, smem);
        do_layer<384, 12, 10, 3, 1152 * 1024>(t, tid, group, rank, cbase, xt, smem);

        // ---- output projection: rank0 only (owns s_out) ----
        if (rank == 0) {
            float acc = 0.f;
#pragma unroll
            for (int qq = 0; qq < 32; ++qq) {
                int qv = qq * 4 + p_seg;
                acc = fmaf(s_out[qv * 16 + p_r], s_wout[p_o * WOUT_S + qv], acc);
            }
            acc += __shfl_down_sync(0xffffffffu, acc, 2, 4);
            acc += __shfl_down_sync(0xffffffffu, acc, 1, 4);
            if (p_seg == 0) {
                out[((size_t)t * BATCH + row0 + p_r) * OUT_F + p_o] = acc + bo;
            }
        }
        // next iteration's sync A protects s_out / smem reuse
    }
}

extern "C" void kernel_launch(void* const* d_in, const int* in_sizes, int n_in,
                              void* d_out, int out_size)
{
    (void)in_sizes; (void)n_in; (void)out_size;

    cudaFuncSetAttribute(rnn_stack_kernel,
                         cudaFuncAttributeMaxDynamicSharedMemorySize, SM_TOTAL);

    dim3 pgrid((1024 * 448 + 255) / 256, 4);
    prep_kernel<<<pgrid, 256>>>(
        (const float*)d_in[1], (const float*)d_in[3],
        (const float*)d_in[5], (const float*)d_in[7]);

    rnn_stack_kernel<<<NCTA, NTHR, SM_TOTAL>>>(
        (const float*)d_in[0],
        (const float*)d_in[2], (const float*)d_in[4],
        (const float*)d_in[6], (const float*)d_in[8],
        (const float*)d_in[9], (const float*)d_in[10],
        (float*)d_out);
}

// round 11
// speedup vs baseline: 1.4104x; 1.4104x over previous
#include <cuda_runtime.h>
#include <math.h>

// ---------------------------------------------------------------------------
// DilatedSparseRnnStack — R11 (base R8): double-buffered xh with epilogue
// writing the out-section directly into the next layer's buffer (sync A and
// the out staging copy deleted; 13 -> 9 barriers/step); gate-pair packed
// GEMM (ulonglong2 weight load, zero dup-MOVs; dup-pair broadcast xh);
// fast sigmoid/tanh. State layout and everything else from R8.
// ---------------------------------------------------------------------------

namespace {
constexpr int T_STEPS = 256;
constexpr int BATCH   = 1024;
constexpr int IN_F    = 64;
constexpr int HSZ     = 128;
constexpr int OSZ     = 128;
constexpr int OUT_F   = 8;
constexpr int RPC     = 8;
constexpr int NCTA    = BATCH / RPC;   // 128
constexpr int NTHR    = 512;
constexpr int KTOT    = 320 + 384 + 448 + 384;  // 1536

// dynamic SMEM layout (bytes); xh buffers hold dup-pairs: float2[k*8 + r]
constexpr int SM_XH0   = 0;         // 448*8*8 = 28672
constexpr int SM_XH1   = 28672;     // 28672
constexpr int SM_RED   = 57344;     // 16*256*8 = 32768
constexpr int SM_OUT   = 90112;     // 4096 (plain float [j*8+r])
constexpr int SM_WOUT  = 94208;     // 4096
constexpr int SM_TOTAL = 98304;
}

// Transposed, gate-interleaved weights: per layer [K][1024], fast index 4*j+g.
// 16B at (k,j) = {g0,g1,g2,g3} -> ulonglong2 {(g0,g1),(g2,g3)}.
__device__ float g_WT[(size_t)KTOT * 1024];

// Circular dilation buffers, CTA-local layout (slot offsets {0,1,4,10}):
//   C: [slot 22][group 128][j 256][r 8]   H: [slot 22][group 128][jh 128][r 8]
__device__ float4 g_bufC4[22u * 128 * 256 * 2];
__device__ float4 g_bufH4[22u * 128 * 128 * 2];

__device__ __forceinline__ float sigf(float v) {
    return __fdividef(1.0f, 1.0f + __expf(-v));
}
__device__ __forceinline__ float tanh_fast(float v) {
    return __fdividef(2.0f, 1.0f + __expf(-2.0f * v)) - 1.0f;
}
__device__ __forceinline__ void ffma2(unsigned long long& d,
                                      unsigned long long a,
                                      unsigned long long b) {
    asm("fma.rn.f32x2 %0, %1, %2, %0;" : "+l"(d) : "l"(a), "l"(b));
}
__device__ __forceinline__ void fadd2(unsigned long long& d,
                                      unsigned long long a) {
    asm("add.rn.f32x2 %0, %0, %1;" : "+l"(d) : "l"(a));
}
__device__ __forceinline__ float2 u2f2(unsigned long long v) {
    float2 f;
    asm("mov.b64 {%0, %1}, %2;" : "=f"(f.x), "=f"(f.y) : "l"(v));
    return f;
}

// ---------------------------------------------------------------------------
// Prep: transpose + gate-interleave weights (read-coalesced over W).
// ---------------------------------------------------------------------------
__global__ void prep_kernel(const float* __restrict__ W0,
                            const float* __restrict__ W1,
                            const float* __restrict__ W2,
                            const float* __restrict__ W3)
{
    const int li = blockIdx.y;
    const float* W;
    int K, off;
    if (li == 0)      { W = W0; K = 320; off = 0; }
    else if (li == 1) { W = W1; K = 384; off = 320 * 1024; }
    else if (li == 2) { W = W2; K = 448; off = 704 * 1024; }
    else              { W = W3; K = 384; off = 1152 * 1024; }

    int idx = blockIdx.x * 256 + threadIdx.x;
    if (idx < 1024 * K) {
        int row = idx / K;           // g*256 + j
        int k   = idx - row * K;
        int g = row >> 8, j = row & 255;
        g_WT[(size_t)off + (size_t)k * 1024 + 4 * j + g] = W[idx];
    }
}

// ---------------------------------------------------------------------------
// One layer step. 512 threads: half = tid>>8 (k-half; owns rows 4h..4h+3),
// j = tid&255 (gate-state column).
// xh for THIS layer = buf[LI&1]; epilogue writes out-dups into buf[(LI+1)&1].
// Layer xh layouts (k offsets):
//   L0: x@0(64)  H@64        L1: out@0 H@128
//   L2: out@0 x@128 H@192    L3: out@0 H@128
// ---------------------------------------------------------------------------
template <int K, int DIL, int LOFF, int LI, int WTOFF>
__device__ __forceinline__ void do_layer(
    int t, int tid, int group,
    const float* __restrict__ xt,
    float4 bias,
    char* __restrict__ smem)
{
    const int prevSlot = LOFF + (t - 1 + DIL) % DIL;
    const int curSlot  = LOFF + (t % DIL);
    const int half = tid >> 8;
    const int j    = tid & 255;

    float2* xh2 = reinterpret_cast<float2*>(
        smem + ((LI & 1) ? SM_XH1 : SM_XH0));
    unsigned long long* s_red =
        reinterpret_cast<unsigned long long*>(smem + SM_RED);
    float4* s_out4 = reinterpret_cast<float4*>(smem + SM_OUT);

    // ---- C-state prefetch: float4 = owned rows 4h..4h+3 of col j ----
    const size_t cIdx = ((size_t)(curSlot  * 128 + group) * 256 + j) * 2 + half;
    const size_t pIdx = ((size_t)(prevSlot * 128 + group) * 256 + j) * 2 + half;
    float4 pC4 = make_float4(0.f, 0.f, 0.f, 0.f);
    float4 dC4 = make_float4(0.f, 0.f, 0.f, 0.f);
    if (t > 0)    pC4 = g_bufC4[pIdx];
    if (t >= DIL) dC4 = g_bufC4[cIdx];

    // ---- stage x section (layers 0,2): dup-pairs ----
    if (LI == 0 || LI == 2) {
        constexpr int XOFF = (LI == 0) ? 0 : OSZ;
        if (tid < 128) {
            int r = tid & 7, k4 = tid >> 3;          // k4 in 0..15
            const float4 v = reinterpret_cast<const float4*>(xt)[r * 16 + k4];
            int b = (XOFF + 4 * k4) * 8 + r;
            xh2[b]      = make_float2(v.x, v.x);
            xh2[b + 8]  = make_float2(v.y, v.y);
            xh2[b + 16] = make_float2(v.z, v.z);
            xh2[b + 24] = make_float2(v.w, v.w);
        }
    }
    // ---- stage prevH (sel 0) / dH (sel 1): coalesced LDG.128 -> dup STS ----
    {
        constexpr int HOFF = (LI == 0) ? IN_F : (LI == 2) ? (OSZ + IN_F) : OSZ;
        const int sel = tid >> 8;
        const int jj  = tid & 255;
        const int slotH = (sel == 0) ? prevSlot
                                     : ((t >= DIL) ? curSlot : prevSlot);
        float4 v = make_float4(0.f, 0.f, 0.f, 0.f);
        if (t > 0) {
            v = g_bufH4[((size_t)(slotH * 128 + group) * 128) * 2 + jj];
        }
        const int jh = jj >> 1, r0 = (jj & 1) * 4;
        const int dst = (HOFF + sel * HSZ + jh) * 8 + r0;
        *reinterpret_cast<float4*>(&xh2[dst]) =
            make_float4(v.x, v.x, v.y, v.y);
        *reinterpret_cast<float4*>(&xh2[dst + 2]) =
            make_float4(v.z, v.z, v.w, v.w);
    }

    __syncthreads();  // sync B: xh complete (incl. prev layer's out-dups)

    // ---- GEMM over this half's k-range: gate-pair packing ----
    // a01[r] = (g0,g1) accum of row r; a23[r] = (g2,g3).
    unsigned long long a01[8], a23[8];
#pragma unroll
    for (int r = 0; r < 8; ++r) { a01[r] = 0ull; a23[r] = 0ull; }

    {
        const char* wp = reinterpret_cast<const char*>(g_WT + WTOFF)
                       + (size_t)j * 16 + (size_t)half * (K / 2) * 4096;
        const char* xp = reinterpret_cast<const char*>(xh2)
                       + half * (K / 2) * 64;
        for (int kb = 0; kb < K / 2; kb += 8) {
#pragma unroll
            for (int u = 0; u < 8; ++u) {
                ulonglong2 w = *reinterpret_cast<const ulonglong2*>(wp + u * 4096);
                ulonglong2 xA = *reinterpret_cast<const ulonglong2*>(xp + u * 64);
                ulonglong2 xB = *reinterpret_cast<const ulonglong2*>(xp + u * 64 + 16);
                ffma2(a01[0], w.x, xA.x); ffma2(a23[0], w.y, xA.x);
                ffma2(a01[1], w.x, xA.y); ffma2(a23[1], w.y, xA.y);
                ffma2(a01[2], w.x, xB.x); ffma2(a23[2], w.y, xB.x);
                ffma2(a01[3], w.x, xB.y); ffma2(a23[3], w.y, xB.y);
                ulonglong2 xC = *reinterpret_cast<const ulonglong2*>(xp + u * 64 + 32);
                ulonglong2 xD = *reinterpret_cast<const ulonglong2*>(xp + u * 64 + 48);
                ffma2(a01[4], w.x, xC.x); ffma2(a23[4], w.y, xC.x);
                ffma2(a01[5], w.x, xC.y); ffma2(a23[5], w.y, xC.y);
                ffma2(a01[6], w.x, xD.x); ffma2(a23[6], w.y, xD.x);
                ffma2(a01[7], w.x, xD.y); ffma2(a23[7], w.y, xD.y);
            }
            wp += 8 * 4096;
            xp += 8 * 64;
        }
    }

    // ---- write partials for NON-owned rows (single writer per slot) ----
    {
        const int ro = (1 - half) * 4;
#pragma unroll
        for (int i = 0; i < 4; ++i) {
            s_red[(ro + i) * 256 + j]       = a01[ro + i];
            s_red[(8 + ro + i) * 256 + j]   = a23[ro + i];
        }
    }

    __syncthreads();  // sync D: partials visible

    {
        const int rm = half * 4;
#pragma unroll
        for (int i = 0; i < 4; ++i) {
            fadd2(a01[rm + i], s_red[(rm + i) * 256 + j]);
            fadd2(a23[rm + i], s_red[(8 + rm + i) * 256 + j]);
        }
    }

    // ---- epilogue: owned rows 4h..4h+3 of col j ----
    const float* pCf = &pC4.x;
    const float* dCf = &dC4.x;
    float nc[4], wh[4];
#pragma unroll
    for (int i = 0; i < 4; ++i) {
        const int row = half * 4 + i;
        float2 G01 = u2f2(a01[row]);
        float2 G23 = u2f2(a23[row]);
        float forget = sigf(G01.x + bias.x + 1.0f);
        float cand   = tanh_fast(G01.y + bias.y);
        float alpha  = sigf(G23.x + bias.z);
        float og     = sigf(G23.y + bias.w);
        float newC;
        if (t == 0) {
            newC = cand;
        } else {
            float wC = pCf[i];
            if (t >= DIL) {
                wC = alpha * pCf[i] + (1.0f - alpha) * dCf[i];
            }
            newC = forget * wC + (1.0f - forget) * cand;
        }
        nc[i] = newC;
        wh[i] = og * newC;
    }
    g_bufC4[cIdx] = make_float4(nc[0], nc[1], nc[2], nc[3]);
    if (j < OSZ) {
        if (LI < 3) {
            // write dup-pairs directly into the NEXT layer's xh out-section
            float4* xn = reinterpret_cast<float4*>(
                smem + ((LI & 1) ? SM_XH0 : SM_XH1));
            xn[j * 4 + 2 * half]     = make_float4(wh[0], wh[0], wh[1], wh[1]);
            xn[j * 4 + 2 * half + 1] = make_float4(wh[2], wh[2], wh[3], wh[3]);
        } else {
            s_out4[j * 2 + half] = make_float4(wh[0], wh[1], wh[2], wh[3]);
        }
    } else {
        g_bufH4[((size_t)(curSlot * 128 + group) * 128 + (j - OSZ)) * 2 + half] =
            make_float4(wh[0], wh[1], wh[2], wh[3]);
    }
}

__global__ __launch_bounds__(NTHR, 1) void rnn_stack_kernel(
    const float* __restrict__ x,
    const float* __restrict__ b0, const float* __restrict__ b1,
    const float* __restrict__ b2, const float* __restrict__ b3,
    const float* __restrict__ Wout, const float* __restrict__ bout,
    float* __restrict__ out)
{
    extern __shared__ char smem[];
    float* s_out  = reinterpret_cast<float*>(smem + SM_OUT);
    float* s_wout = reinterpret_cast<float*>(smem + SM_WOUT);

    const int tid   = threadIdx.x;
    const int group = blockIdx.x;
    const int row0  = group * RPC;
    const int j     = tid & 255;

    if (tid < 256) {
        reinterpret_cast<float4*>(s_wout)[tid] =
            reinterpret_cast<const float4*>(Wout)[tid];
    }
    float4 bs0 = make_float4(b0[j], b0[256 + j], b0[512 + j], b0[768 + j]);
    float4 bs1 = make_float4(b1[j], b1[256 + j], b1[512 + j], b1[768 + j]);
    float4 bs2 = make_float4(b2[j], b2[256 + j], b2[512 + j], b2[768 + j]);
    float4 bs3 = make_float4(b3[j], b3[256 + j], b3[512 + j], b3[768 + j]);

    // projection mapping: seg = tid&7 (k-segment), o = (tid>>3)&7, r = tid>>6
    const int p_seg = tid & 7;
    const int p_o   = (tid >> 3) & 7;
    const int p_r   = tid >> 6;
    const float bo  = bout[p_o];

    for (int t = 0; t < T_STEPS; ++t) {
        const float* xt = x + ((size_t)t * BATCH + row0) * IN_F;

        do_layer<320,  1,  0, 0, 0>          (t, tid, group, xt, bs0, smem);
        do_layer<384,  3,  1, 1, 320 * 1024> (t, tid, group, xt, bs1, smem);
        do_layer<448,  6,  4, 2, 704 * 1024> (t, tid, group, xt, bs2, smem);
        do_layer<384, 12, 10, 3, 1152 * 1024>(t, tid, group, xt, bs3, smem);

        __syncthreads();  // sync P: layer-3 s_out ready

        // ---- output projection: all 512 threads, shfl octet reduction ----
        {
            float acc = 0.f;
#pragma unroll
            for (int qq = 0; qq < 16; ++qq) {
                int qv = qq * 8 + p_seg;
                acc = fmaf(s_out[qv * 8 + p_r], s_wout[p_o * OSZ + qv], acc);
            }
            acc += __shfl_down_sync(0xffffffffu, acc, 4, 8);
            acc += __shfl_down_sync(0xffffffffu, acc, 2, 8);
            acc += __shfl_down_sync(0xffffffffu, acc, 1, 8);
            if (p_seg == 0) {
                out[((size_t)t * BATCH + row0 + p_r) * OUT_F + p_o] = acc + bo;
            }
        }
        // double-buffered xh + s_red write/read fencing make sync A unnecessary
    }
}

extern "C" void kernel_launch(void* const* d_in, const int* in_sizes, int n_in,
                              void* d_out, int out_size)
{
    (void)in_sizes; (void)n_in; (void)out_size;

    cudaFuncSetAttribute(rnn_stack_kernel,
                         cudaFuncAttributeMaxDynamicSharedMemorySize, SM_TOTAL);

    dim3 pgrid((1024 * 448 + 255) / 256, 4);
    prep_kernel<<<pgrid, 256>>>(
        (const float*)d_in[1], (const float*)d_in[3],
        (const float*)d_in[5], (const float*)d_in[7]);

    rnn_stack_kernel<<<NCTA, NTHR, SM_TOTAL>>>(
        (const float*)d_in[0],
        (const float*)d_in[2], (const float*)d_in[4],
        (const float*)d_in[6], (const float*)d_in[8],
        (const float*)d_in[9], (const float*)d_in[10],
        (float*)d_out);
}

// round 12
// speedup vs baseline: 1.8418x; 1.3058x over previous
#include <cuda_runtime.h>
#include <math.h>

// ---------------------------------------------------------------------------
// DilatedSparseRnnStack — R12: R8 verbatim (un-duplicated xh GEMM, dup-MOV
// weights, coalesced state layout) + double-buffered xh with direct epilogue
// out-writes (sync A and out staging deleted; 13 -> 9 barriers/step) + fast
// sigmoid/tanh in the epilogue.
// ---------------------------------------------------------------------------

namespace {
constexpr int T_STEPS = 256;
constexpr int BATCH   = 1024;
constexpr int IN_F    = 64;
constexpr int HSZ     = 128;
constexpr int OSZ     = 128;
constexpr int OUT_F   = 8;
constexpr int RPC     = 8;
constexpr int NCTA    = BATCH / RPC;   // 128
constexpr int NTHR    = 512;
constexpr int KTOT    = 320 + 384 + 448 + 384;  // 1536

// dynamic SMEM layout (bytes); xh buffers: un-dup floats [k*8 + r]
constexpr int SM_XH0   = 0;         // 448*8*4 = 14336
constexpr int SM_XH1   = 14336;     // 14336
constexpr int SM_RED   = 28672;     // 16*256*8 = 32768
constexpr int SM_OUT   = 61440;     // 4096
constexpr int SM_WOUT  = 65536;     // 4096
constexpr int SM_TOTAL = 69632;
}

// Transposed, gate-interleaved weights: per layer [K][1024], fast index 4*j+g.
__device__ float g_WT[(size_t)KTOT * 1024];

// Circular dilation buffers, CTA-local layout (slot offsets {0,1,4,10}):
//   C: [slot 22][group 128][j 256][r 8]   H: [slot 22][group 128][jh 128][r 8]
__device__ float4 g_bufC4[22u * 128 * 256 * 2];
__device__ float4 g_bufH4[22u * 128 * 128 * 2];

__device__ __forceinline__ float sigf(float v) {
    return __fdividef(1.0f, 1.0f + __expf(-v));
}
__device__ __forceinline__ float tanh_fast(float v) {
    return __fdividef(2.0f, 1.0f + __expf(-2.0f * v)) - 1.0f;
}
__device__ __forceinline__ void ffma2(unsigned long long& d,
                                      unsigned long long a,
                                      unsigned long long b) {
    asm("fma.rn.f32x2 %0, %1, %2, %0;" : "+l"(d) : "l"(a), "l"(b));
}
__device__ __forceinline__ void fadd2(unsigned long long& d,
                                      unsigned long long a) {
    asm("add.rn.f32x2 %0, %0, %1;" : "+l"(d) : "l"(a));
}
__device__ __forceinline__ unsigned long long dup2(float w) {
    unsigned long long r;
    asm("mov.b64 %0, {%1, %1};" : "=l"(r) : "f"(w));
    return r;
}
__device__ __forceinline__ float2 u2f2(unsigned long long v) {
    float2 f;
    asm("mov.b64 {%0, %1}, %2;" : "=f"(f.x), "=f"(f.y) : "l"(v));
    return f;
}

// ---------------------------------------------------------------------------
// Prep: transpose + gate-interleave weights (read-coalesced over W).
// ---------------------------------------------------------------------------
__global__ void prep_kernel(const float* __restrict__ W0,
                            const float* __restrict__ W1,
                            const float* __restrict__ W2,
                            const float* __restrict__ W3)
{
    const int li = blockIdx.y;
    const float* W;
    int K, off;
    if (li == 0)      { W = W0; K = 320; off = 0; }
    else if (li == 1) { W = W1; K = 384; off = 320 * 1024; }
    else if (li == 2) { W = W2; K = 448; off = 704 * 1024; }
    else              { W = W3; K = 384; off = 1152 * 1024; }

    int idx = blockIdx.x * 256 + threadIdx.x;
    if (idx < 1024 * K) {
        int row = idx / K;           // g*256 + j
        int k   = idx - row * K;
        int g = row >> 8, j = row & 255;
        g_WT[(size_t)off + (size_t)k * 1024 + 4 * j + g] = W[idx];
    }
}

// ---------------------------------------------------------------------------
// One layer step. 512 threads: half = tid>>8 (k-half; owns rows 4h..4h+3),
// j = tid&255.
// xh buffer for THIS layer = buf[LI&1]; epilogue writes the out-section
// directly into buf[(LI+1)&1] for the next layer. Layer xh k-offsets:
//   L0(buf0): x@0  H@64      L1(buf1): out@0 H@128
//   L2(buf0): out@0 x@128 H@192   L3(buf1): out@0 H@128
// ---------------------------------------------------------------------------
template <int K, int DIL, int LOFF, int LI, int WTOFF>
__device__ __forceinline__ void do_layer(
    int t, int tid, int group,
    const float* __restrict__ xt,
    float4 bias,
    char* __restrict__ smem)
{
    const int prevSlot = LOFF + (t - 1 + DIL) % DIL;
    const int curSlot  = LOFF + (t % DIL);
    const int half = tid >> 8;
    const int j    = tid & 255;

    float* s_xhf = reinterpret_cast<float*>(
        smem + ((LI & 1) ? SM_XH1 : SM_XH0));
    unsigned long long* s_red =
        reinterpret_cast<unsigned long long*>(smem + SM_RED);
    float* s_out = reinterpret_cast<float*>(smem + SM_OUT);

    // ---- C-state prefetch: float4 = owned rows 4h..4h+3 of col j ----
    const size_t cIdx = ((size_t)(curSlot  * 128 + group) * 256 + j) * 2 + half;
    const size_t pIdx = ((size_t)(prevSlot * 128 + group) * 256 + j) * 2 + half;
    float4 pC4 = make_float4(0.f, 0.f, 0.f, 0.f);
    float4 dC4 = make_float4(0.f, 0.f, 0.f, 0.f);
    if (t > 0)    pC4 = g_bufC4[pIdx];
    if (t >= DIL) dC4 = g_bufC4[cIdx];

    // ---- stage x section (layers 0,2) ----
    if (LI == 0 || LI == 2) {
        constexpr int XOFF = (LI == 0) ? 0 : OSZ;
        if (tid < 128) {
            int r = tid & 7, k4 = tid >> 3;          // k4 in 0..15
            const float4 v = reinterpret_cast<const float4*>(xt)[r * 16 + k4];
            int b = (XOFF + 4 * k4) * 8 + r;
            s_xhf[b]      = v.x;
            s_xhf[b + 8]  = v.y;
            s_xhf[b + 16] = v.z;
            s_xhf[b + 24] = v.w;
        }
    }
    // ---- stage prevH (sel 0) / dH (sel 1): coalesced LDG.128 -> STS.128 ----
    {
        constexpr int HOFF = (LI == 0) ? IN_F : (LI == 2) ? (OSZ + IN_F) : OSZ;
        const int sel = tid >> 8;
        const int jj  = tid & 255;
        const int slotH = (sel == 0) ? prevSlot
                                     : ((t >= DIL) ? curSlot : prevSlot);
        float4 v = make_float4(0.f, 0.f, 0.f, 0.f);
        if (t > 0) {
            v = g_bufH4[((size_t)(slotH * 128 + group) * 128) * 2 + jj];
        }
        const int jh = jj >> 1, r0 = (jj & 1) * 4;
        const int dst = (HOFF + sel * HSZ + jh) * 8 + r0;
        *reinterpret_cast<float4*>(&s_xhf[dst]) = v;
    }

    __syncthreads();  // sync B: xh complete (incl. prev layer's direct writes)

    // ---- GEMM over this half's k-range (row-pair packing, un-dup xh) ----
    unsigned long long a01[8], a23[8];  // a01: (g0,g1)? no: a01[r]=rows pair
    // a01[p] etc as in R8: aG0..aG3 per gate; keep R8 naming
    unsigned long long aG0[4], aG1[4], aG2[4], aG3[4];
#pragma unroll
    for (int p = 0; p < 4; ++p) { aG0[p] = aG1[p] = aG2[p] = aG3[p] = 0ull; }
    (void)a01; (void)a23;

    {
        const char* wp = reinterpret_cast<const char*>(g_WT + WTOFF)
                       + (size_t)j * 16 + (size_t)half * (K / 2) * 4096;
        const char* xp = reinterpret_cast<const char*>(s_xhf)
                       + half * (K / 2) * 32;
        for (int kb = 0; kb < K / 2; kb += 8) {
#pragma unroll
            for (int u = 0; u < 8; ++u) {
                float4 w = *reinterpret_cast<const float4*>(wp + u * 4096);
                ulonglong2 xA = *reinterpret_cast<const ulonglong2*>(xp + u * 32);
                ulonglong2 xB = *reinterpret_cast<const ulonglong2*>(xp + u * 32 + 16);
                unsigned long long w0 = dup2(w.x);
                unsigned long long w1 = dup2(w.y);
                unsigned long long w2 = dup2(w.z);
                unsigned long long w3 = dup2(w.w);
                ffma2(aG0[0], w0, xA.x); ffma2(aG0[1], w0, xA.y);
                ffma2(aG0[2], w0, xB.x); ffma2(aG0[3], w0, xB.y);
                ffma2(aG1[0], w1, xA.x); ffma2(aG1[1], w1, xA.y);
                ffma2(aG1[2], w1, xB.x); ffma2(aG1[3], w1, xB.y);
                ffma2(aG2[0], w2, xA.x); ffma2(aG2[1], w2, xA.y);
                ffma2(aG2[2], w2, xB.x); ffma2(aG2[3], w2, xB.y);
                ffma2(aG3[0], w3, xA.x); ffma2(aG3[1], w3, xA.y);
                ffma2(aG3[2], w3, xB.x); ffma2(aG3[3], w3, xB.y);
            }
            wp += 8 * 4096;
            xp += 8 * 32;
        }
    }

    // ---- write partials for NON-owned row-pairs (fenced by sync B above) ----
    {
        const int po = 2 - 2 * half;   // other half's first pair
#pragma unroll
        for (int i = 0; i < 2; ++i) {
            s_red[((0 * 4) + po + i) * 256 + j] = aG0[po + i];
            s_red[((1 * 4) + po + i) * 256 + j] = aG1[po + i];
            s_red[((2 * 4) + po + i) * 256 + j] = aG2[po + i];
            s_red[((3 * 4) + po + i) * 256 + j] = aG3[po + i];
        }
    }

    __syncthreads();  // sync D: partials visible

    {
        const int pm = 2 * half;       // my first pair
#pragma unroll
        for (int i = 0; i < 2; ++i) {
            fadd2(aG0[pm + i], s_red[((0 * 4) + pm + i) * 256 + j]);
            fadd2(aG1[pm + i], s_red[((1 * 4) + pm + i) * 256 + j]);
            fadd2(aG2[pm + i], s_red[((2 * 4) + pm + i) * 256 + j]);
            fadd2(aG3[pm + i], s_red[((3 * 4) + pm + i) * 256 + j]);
        }
    }

    // ---- epilogue: owned rows 4h..4h+3 of col j ----
    const float* pCf = &pC4.x;
    const float* dCf = &dC4.x;
    float nc[4], wh[4];
#pragma unroll
    for (int i = 0; i < 2; ++i) {
        const int p = 2 * half + i;
        float2 G0 = u2f2(aG0[p]);
        float2 G1 = u2f2(aG1[p]);
        float2 G2 = u2f2(aG2[p]);
        float2 G3 = u2f2(aG3[p]);
#pragma unroll
        for (int s = 0; s < 2; ++s) {
            const int r = 2 * i + s;
            float forget = sigf((s ? G0.y : G0.x) + bias.x + 1.0f);
            float cand   = tanh_fast((s ? G1.y : G1.x) + bias.y);
            float alpha  = sigf((s ? G2.y : G2.x) + bias.z);
            float og     = sigf((s ? G3.y : G3.x) + bias.w);
            float newC;
            if (t == 0) {
                newC = cand;
            } else {
                float wC = pCf[r];
                if (t >= DIL) {
                    wC = alpha * pCf[r] + (1.0f - alpha) * dCf[r];
                }
                newC = forget * wC + (1.0f - forget) * cand;
            }
            nc[r] = newC;
            wh[r] = og * newC;
        }
    }
    g_bufC4[cIdx] = make_float4(nc[0], nc[1], nc[2], nc[3]);
    float4 w4 = make_float4(wh[0], wh[1], wh[2], wh[3]);
    if (j < OSZ) {
        if (LI < 3) {
            // direct write into NEXT layer's xh out-section (k-offset 0)
            float* xn = reinterpret_cast<float*>(
                smem + ((LI & 1) ? SM_XH0 : SM_XH1));
            *reinterpret_cast<float4*>(&xn[j * 8 + 4 * half]) = w4;
        } else {
            *reinterpret_cast<float4*>(&s_out[j * 8 + 4 * half]) = w4;
        }
    } else {
        g_bufH4[((size_t)(curSlot * 128 + group) * 128 + (j - OSZ)) * 2 + half] = w4;
    }
}

__global__ __launch_bounds__(NTHR, 1) void rnn_stack_kernel(
    const float* __restrict__ x,
    const float* __restrict__ b0, const float* __restrict__ b1,
    const float* __restrict__ b2, const float* __restrict__ b3,
    const float* __restrict__ Wout, const float* __restrict__ bout,
    float* __restrict__ out)
{
    extern __shared__ char smem[];
    float* s_out  = reinterpret_cast<float*>(smem + SM_OUT);
    float* s_wout = reinterpret_cast<float*>(smem + SM_WOUT);

    const int tid   = threadIdx.x;
    const int group = blockIdx.x;
    const int row0  = group * RPC;
    const int j     = tid & 255;

    if (tid < 256) {
        reinterpret_cast<float4*>(s_wout)[tid] =
            reinterpret_cast<const float4*>(Wout)[tid];
    }
    float4 bs0 = make_float4(b0[j], b0[256 + j], b0[512 + j], b0[768 + j]);
    float4 bs1 = make_float4(b1[j], b1[256 + j], b1[512 + j], b1[768 + j]);
    float4 bs2 = make_float4(b2[j], b2[256 + j], b2[512 + j], b2[768 + j]);
    float4 bs3 = make_float4(b3[j], b3[256 + j], b3[512 + j], b3[768 + j]);

    // projection mapping: seg = tid&7 (k-segment), o = (tid>>3)&7, r = tid>>6
    const int p_seg = tid & 7;
    const int p_o   = (tid >> 3) & 7;
    const int p_r   = tid >> 6;
    const float bo  = bout[p_o];

    for (int t = 0; t < T_STEPS; ++t) {
        const float* xt = x + ((size_t)t * BATCH + row0) * IN_F;

        do_layer<320,  1,  0, 0, 0>          (t, tid, group, xt, bs0, smem);
        do_layer<384,  3,  1, 1, 320 * 1024> (t, tid, group, xt, bs1, smem);
        do_layer<448,  6,  4, 2, 704 * 1024> (t, tid, group, xt, bs2, smem);
        do_layer<384, 12, 10, 3, 1152 * 1024>(t, tid, group, xt, bs3, smem);

        __syncthreads();  // sync P: layer-3 s_out ready; fences buffer reuse

        // ---- output projection: all 512 threads, shfl octet reduction ----
        {
            float acc = 0.f;
#pragma unroll
            for (int qq = 0; qq < 16; ++qq) {
                int qv = qq * 8 + p_seg;
                acc = fmaf(s_out[qv * 8 + p_r], s_wout[p_o * OSZ + qv], acc);
            }
            acc += __shfl_down_sync(0xffffffffu, acc, 4, 8);
            acc += __shfl_down_sync(0xffffffffu, acc, 2, 8);
            acc += __shfl_down_sync(0xffffffffu, acc, 1, 8);
            if (p_seg == 0) {
                out[((size_t)t * BATCH + row0 + p_r) * OUT_F + p_o] = acc + bo;
            }
        }
        // next layer-0 sync B fences staging vs this projection's s_out reads?
        // s_out is only rewritten by layer-3's epilogue, which is after 8
        // intervening barriers — safe.
    }
}

extern "C" void kernel_launch(void* const* d_in, const int* in_sizes, int n_in,
                              void* d_out, int out_size)
{
    (void)in_sizes; (void)n_in; (void)out_size;

    cudaFuncSetAttribute(rnn_stack_kernel,
                         cudaFuncAttributeMaxDynamicSharedMemorySize, SM_TOTAL);

    dim3 pgrid((1024 * 448 + 255) / 256, 4);
    prep_kernel<<<pgrid, 256>>>(
        (const float*)d_in[1], (const float*)d_in[3],
        (const float*)d_in[5], (const float*)d_in[7]);

    rnn_stack_kernel<<<NCTA, NTHR, SM_TOTAL>>>(
        (const float*)d_in[0],
        (const float*)d_in[2], (const float*)d_in[4],
        (const float*)d_in[6], (const float*)d_in[8],
        (const float*)d_in[9], (const float*)d_in[10],
        (float*)d_out);
}

// round 13
// speedup vs baseline: 1.8819x; 1.0218x over previous
#include <cuda_runtime.h>
#include <math.h>

// ---------------------------------------------------------------------------
// DilatedSparseRnnStack — R13: R12 + explicit 8-deep weight-load ring
// (prologue issued BEFORE staging/sync so L2 latency hides under the barrier;
// steady-state MLP=8 per warp) + ulonglong2 reduction exchange.
// ---------------------------------------------------------------------------

namespace {
constexpr int T_STEPS = 256;
constexpr int BATCH   = 1024;
constexpr int IN_F    = 64;
constexpr int HSZ     = 128;
constexpr int OSZ     = 128;
constexpr int OUT_F   = 8;
constexpr int RPC     = 8;
constexpr int NCTA    = BATCH / RPC;   // 128
constexpr int NTHR    = 512;
constexpr int KTOT    = 320 + 384 + 448 + 384;  // 1536

// dynamic SMEM layout (bytes); xh buffers: un-dup floats [k*8 + r]
constexpr int SM_XH0   = 0;         // 448*8*4 = 14336
constexpr int SM_XH1   = 14336;     // 14336
constexpr int SM_RED   = 28672;     // 8*256*16 = 32768
constexpr int SM_OUT   = 61440;     // 4096
constexpr int SM_WOUT  = 65536;     // 4096
constexpr int SM_TOTAL = 69632;
}

// Transposed, gate-interleaved weights: per layer [K][1024], fast index 4*j+g.
// Padded by 16384 floats (64KB) so the ring prefetch may harmlessly over-read.
__device__ float g_WT[(size_t)KTOT * 1024 + 16384];

// Circular dilation buffers, CTA-local layout (slot offsets {0,1,4,10}):
//   C: [slot 22][group 128][j 256][r 8]   H: [slot 22][group 128][jh 128][r 8]
__device__ float4 g_bufC4[22u * 128 * 256 * 2];
__device__ float4 g_bufH4[22u * 128 * 128 * 2];

__device__ __forceinline__ float sigf(float v) {
    return __fdividef(1.0f, 1.0f + __expf(-v));
}
__device__ __forceinline__ float tanh_fast(float v) {
    return __fdividef(2.0f, 1.0f + __expf(-2.0f * v)) - 1.0f;
}
__device__ __forceinline__ void ffma2(unsigned long long& d,
                                      unsigned long long a,
                                      unsigned long long b) {
    asm("fma.rn.f32x2 %0, %1, %2, %0;" : "+l"(d) : "l"(a), "l"(b));
}
__device__ __forceinline__ void fadd2(unsigned long long& d,
                                      unsigned long long a) {
    asm("add.rn.f32x2 %0, %0, %1;" : "+l"(d) : "l"(a));
}
__device__ __forceinline__ unsigned long long dup2(float w) {
    unsigned long long r;
    asm("mov.b64 %0, {%1, %1};" : "=l"(r) : "f"(w));
    return r;
}
__device__ __forceinline__ float2 u2f2(unsigned long long v) {
    float2 f;
    asm("mov.b64 {%0, %1}, %2;" : "=f"(f.x), "=f"(f.y) : "l"(v));
    return f;
}

// ---------------------------------------------------------------------------
// Prep: transpose + gate-interleave weights (read-coalesced over W).
// ---------------------------------------------------------------------------
__global__ void prep_kernel(const float* __restrict__ W0,
                            const float* __restrict__ W1,
                            const float* __restrict__ W2,
                            const float* __restrict__ W3)
{
    const int li = blockIdx.y;
    const float* W;
    int K, off;
    if (li == 0)      { W = W0; K = 320; off = 0; }
    else if (li == 1) { W = W1; K = 384; off = 320 * 1024; }
    else if (li == 2) { W = W2; K = 448; off = 704 * 1024; }
    else              { W = W3; K = 384; off = 1152 * 1024; }

    int idx = blockIdx.x * 256 + threadIdx.x;
    if (idx < 1024 * K) {
        int row = idx / K;           // g*256 + j
        int k   = idx - row * K;
        int g = row >> 8, j = row & 255;
        g_WT[(size_t)off + (size_t)k * 1024 + 4 * j + g] = W[idx];
    }
}

// ---------------------------------------------------------------------------
// One layer step. 512 threads: half = tid>>8 (k-half; owns rows 4h..4h+3),
// j = tid&255. xh buffer = buf[LI&1]; epilogue writes out-section directly
// into buf[(LI+1)&1]. Layer xh k-offsets:
//   L0(buf0): x@0  H@64      L1(buf1): out@0 H@128
//   L2(buf0): out@0 x@128 H@192   L3(buf1): out@0 H@128
// ---------------------------------------------------------------------------
template <int K, int DIL, int LOFF, int LI, int WTOFF>
__device__ __forceinline__ void do_layer(
    int t, int tid, int group,
    const float* __restrict__ xt,
    float4 bias,
    char* __restrict__ smem)
{
    const int prevSlot = LOFF + (t - 1 + DIL) % DIL;
    const int curSlot  = LOFF + (t % DIL);
    const int half = tid >> 8;
    const int j    = tid & 255;

    float* s_xhf = reinterpret_cast<float*>(
        smem + ((LI & 1) ? SM_XH1 : SM_XH0));
    ulonglong2* s_red2 = reinterpret_cast<ulonglong2*>(smem + SM_RED);
    float* s_out = reinterpret_cast<float*>(smem + SM_OUT);

    // ---- C-state prefetch: float4 = owned rows 4h..4h+3 of col j ----
    const size_t cIdx = ((size_t)(curSlot  * 128 + group) * 256 + j) * 2 + half;
    const size_t pIdx = ((size_t)(prevSlot * 128 + group) * 256 + j) * 2 + half;
    float4 pC4 = make_float4(0.f, 0.f, 0.f, 0.f);
    float4 dC4 = make_float4(0.f, 0.f, 0.f, 0.f);
    if (t > 0)    pC4 = g_bufC4[pIdx];
    if (t >= DIL) dC4 = g_bufC4[cIdx];

    // ---- weight ring prologue: 8 LDG.128 in flight before staging+barrier ----
    const char* wp = reinterpret_cast<const char*>(g_WT + WTOFF)
                   + (size_t)j * 16 + (size_t)half * (K / 2) * 4096;
    float4 wr[8];
#pragma unroll
    for (int u = 0; u < 8; ++u) {
        wr[u] = *reinterpret_cast<const float4*>(wp + u * 4096);
    }

    // ---- stage x section (layers 0,2) ----
    if (LI == 0 || LI == 2) {
        constexpr int XOFF = (LI == 0) ? 0 : OSZ;
        if (tid < 128) {
            int r = tid & 7, k4 = tid >> 3;          // k4 in 0..15
            const float4 v = reinterpret_cast<const float4*>(xt)[r * 16 + k4];
            int b = (XOFF + 4 * k4) * 8 + r;
            s_xhf[b]      = v.x;
            s_xhf[b + 8]  = v.y;
            s_xhf[b + 16] = v.z;
            s_xhf[b + 24] = v.w;
        }
    }
    // ---- stage prevH (sel 0) / dH (sel 1): coalesced LDG.128 -> STS.128 ----
    {
        constexpr int HOFF = (LI == 0) ? IN_F : (LI == 2) ? (OSZ + IN_F) : OSZ;
        const int sel = tid >> 8;
        const int jj  = tid & 255;
        const int slotH = (sel == 0) ? prevSlot
                                     : ((t >= DIL) ? curSlot : prevSlot);
        float4 v = make_float4(0.f, 0.f, 0.f, 0.f);
        if (t > 0) {
            v = g_bufH4[((size_t)(slotH * 128 + group) * 128) * 2 + jj];
        }
        const int jh = jj >> 1, r0 = (jj & 1) * 4;
        const int dst = (HOFF + sel * HSZ + jh) * 8 + r0;
        *reinterpret_cast<float4*>(&s_xhf[dst]) = v;
    }

    __syncthreads();  // sync B: xh complete (incl. prev layer's direct writes)

    // ---- GEMM: ring-8 pipelined weight loads, row-pair f32x2 math ----
    unsigned long long aG0[4], aG1[4], aG2[4], aG3[4];
#pragma unroll
    for (int p = 0; p < 4; ++p) { aG0[p] = aG1[p] = aG2[p] = aG3[p] = 0ull; }

    {
        const char* xp = reinterpret_cast<const char*>(s_xhf)
                       + half * (K / 2) * 32;
        for (int kb = 0; kb < K / 2; kb += 8) {
#pragma unroll
            for (int u = 0; u < 8; ++u) {
                float4 w = wr[u];
                wr[u] = *reinterpret_cast<const float4*>(wp + (u + 8) * 4096);
                ulonglong2 xA = *reinterpret_cast<const ulonglong2*>(xp + u * 32);
                ulonglong2 xB = *reinterpret_cast<const ulonglong2*>(xp + u * 32 + 16);
                unsigned long long w0 = dup2(w.x);
                unsigned long long w1 = dup2(w.y);
                unsigned long long w2 = dup2(w.z);
                unsigned long long w3 = dup2(w.w);
                ffma2(aG0[0], w0, xA.x); ffma2(aG0[1], w0, xA.y);
                ffma2(aG0[2], w0, xB.x); ffma2(aG0[3], w0, xB.y);
                ffma2(aG1[0], w1, xA.x); ffma2(aG1[1], w1, xA.y);
                ffma2(aG1[2], w1, xB.x); ffma2(aG1[3], w1, xB.y);
                ffma2(aG2[0], w2, xA.x); ffma2(aG2[1], w2, xA.y);
                ffma2(aG2[2], w2, xB.x); ffma2(aG2[3], w2, xB.y);
                ffma2(aG3[0], w3, xA.x); ffma2(aG3[1], w3, xA.y);
                ffma2(aG3[2], w3, xB.x); ffma2(aG3[3], w3, xB.y);
            }
            wp += 8 * 4096;
            xp += 8 * 32;
        }
    }

    // ---- write partials for NON-owned row-pairs (ulonglong2) ----
    {
        const int po = 2 - 2 * half;           // other half's first pair
        const int pp = 1 - half;               // pair-slot index
        s_red2[(0 * 2 + pp) * 256 + j] = make_ulonglong2(aG0[po], aG0[po + 1]);
        s_red2[(1 * 2 + pp) * 256 + j] = make_ulonglong2(aG1[po], aG1[po + 1]);
        s_red2[(2 * 2 + pp) * 256 + j] = make_ulonglong2(aG2[po], aG2[po + 1]);
        s_red2[(3 * 2 + pp) * 256 + j] = make_ulonglong2(aG3[po], aG3[po + 1]);
    }

    __syncthreads();  // sync D: partials visible

    {
        const int pm = 2 * half;               // my first pair
        ulonglong2 v0 = s_red2[(0 * 2 + half) * 256 + j];
        fadd2(aG0[pm], v0.x); fadd2(aG0[pm + 1], v0.y);
        ulonglong2 v1 = s_red2[(1 * 2 + half) * 256 + j];
        fadd2(aG1[pm], v1.x); fadd2(aG1[pm + 1], v1.y);
        ulonglong2 v2 = s_red2[(2 * 2 + half) * 256 + j];
        fadd2(aG2[pm], v2.x); fadd2(aG2[pm + 1], v2.y);
        ulonglong2 v3 = s_red2[(3 * 2 + half) * 256 + j];
        fadd2(aG3[pm], v3.x); fadd2(aG3[pm + 1], v3.y);
    }

    // ---- epilogue: owned rows 4h..4h+3 of col j ----
    const float* pCf = &pC4.x;
    const float* dCf = &dC4.x;
    float nc[4], wh[4];
#pragma unroll
    for (int i = 0; i < 2; ++i) {
        const int p = 2 * half + i;
        float2 G0 = u2f2(aG0[p]);
        float2 G1 = u2f2(aG1[p]);
        float2 G2 = u2f2(aG2[p]);
        float2 G3 = u2f2(aG3[p]);
#pragma unroll
        for (int s = 0; s < 2; ++s) {
            const int r = 2 * i + s;
            float forget = sigf((s ? G0.y : G0.x) + bias.x + 1.0f);
            float cand   = tanh_fast((s ? G1.y : G1.x) + bias.y);
            float alpha  = sigf((s ? G2.y : G2.x) + bias.z);
            float og     = sigf((s ? G3.y : G3.x) + bias.w);
            float newC;
            if (t == 0) {
                newC = cand;
            } else {
                float wC = pCf[r];
                if (t >= DIL) {
                    wC = alpha * pCf[r] + (1.0f - alpha) * dCf[r];
                }
                newC = forget * wC + (1.0f - forget) * cand;
            }
            nc[r] = newC;
            wh[r] = og * newC;
        }
    }
    g_bufC4[cIdx] = make_float4(nc[0], nc[1], nc[2], nc[3]);
    float4 w4 = make_float4(wh[0], wh[1], wh[2], wh[3]);
    if (j < OSZ) {
        if (LI < 3) {
            float* xn = reinterpret_cast<float*>(
                smem + ((LI & 1) ? SM_XH0 : SM_XH1));
            *reinterpret_cast<float4*>(&xn[j * 8 + 4 * half]) = w4;
        } else {
            *reinterpret_cast<float4*>(&s_out[j * 8 + 4 * half]) = w4;
        }
    } else {
        g_bufH4[((size_t)(curSlot * 128 + group) * 128 + (j - OSZ)) * 2 + half] = w4;
    }
}

__global__ __launch_bounds__(NTHR, 1) void rnn_stack_kernel(
    const float* __restrict__ x,
    const float* __restrict__ b0, const float* __restrict__ b1,
    const float* __restrict__ b2, const float* __restrict__ b3,
    const float* __restrict__ Wout, const float* __restrict__ bout,
    float* __restrict__ out)
{
    extern __shared__ char smem[];
    float* s_out  = reinterpret_cast<float*>(smem + SM_OUT);
    float* s_wout = reinterpret_cast<float*>(smem + SM_WOUT);

    const int tid   = threadIdx.x;
    const int group = blockIdx.x;
    const int row0  = group * RPC;
    const int j     = tid & 255;

    if (tid < 256) {
        reinterpret_cast<float4*>(s_wout)[tid] =
            reinterpret_cast<const float4*>(Wout)[tid];
    }
    float4 bs0 = make_float4(b0[j], b0[256 + j], b0[512 + j], b0[768 + j]);
    float4 bs1 = make_float4(b1[j], b1[256 + j], b1[512 + j], b1[768 + j]);
    float4 bs2 = make_float4(b2[j], b2[256 + j], b2[512 + j], b2[768 + j]);
    float4 bs3 = make_float4(b3[j], b3[256 + j], b3[512 + j], b3[768 + j]);

    // projection mapping: seg = tid&7 (k-segment), o = (tid>>3)&7, r = tid>>6
    const int p_seg = tid & 7;
    const int p_o   = (tid >> 3) & 7;
    const int p_r   = tid >> 6;
    const float bo  = bout[p_o];

    for (int t = 0; t < T_STEPS; ++t) {
        const float* xt = x + ((size_t)t * BATCH + row0) * IN_F;

        do_layer<320,  1,  0, 0, 0>          (t, tid, group, xt, bs0, smem);
        do_layer<384,  3,  1, 1, 320 * 1024> (t, tid, group, xt, bs1, smem);
        do_layer<448,  6,  4, 2, 704 * 1024> (t, tid, group, xt, bs2, smem);
        do_layer<384, 12, 10, 3, 1152 * 1024>(t, tid, group, xt, bs3, smem);

        __syncthreads();  // sync P: layer-3 s_out ready; fences buffer reuse

        // ---- output projection: all 512 threads, shfl octet reduction ----
        {
            float acc = 0.f;
#pragma unroll
            for (int qq = 0; qq < 16; ++qq) {
                int qv = qq * 8 + p_seg;
                acc = fmaf(s_out[qv * 8 + p_r], s_wout[p_o * OSZ + qv], acc);
            }
            acc += __shfl_down_sync(0xffffffffu, acc, 4, 8);
            acc += __shfl_down_sync(0xffffffffu, acc, 2, 8);
            acc += __shfl_down_sync(0xffffffffu, acc, 1, 8);
            if (p_seg == 0) {
                out[((size_t)t * BATCH + row0 + p_r) * OUT_F + p_o] = acc + bo;
            }
        }
    }
}

extern "C" void kernel_launch(void* const* d_in, const int* in_sizes, int n_in,
                              void* d_out, int out_size)
{
    (void)in_sizes; (void)n_in; (void)out_size;

    cudaFuncSetAttribute(rnn_stack_kernel,
                         cudaFuncAttributeMaxDynamicSharedMemorySize, SM_TOTAL);

    dim3 pgrid((1024 * 448 + 255) / 256, 4);
    prep_kernel<<<pgrid, 256>>>(
        (const float*)d_in[1], (const float*)d_in[3],
        (const float*)d_in[5], (const float*)d_in[7]);

    rnn_stack_kernel<<<NCTA, NTHR, SM_TOTAL>>>(
        (const float*)d_in[0],
        (const float*)d_in[2], (const float*)d_in[4],
        (const float*)d_in[6], (const float*)d_in[8],
        (const float*)d_in[9], (const float*)d_in[10],
        (float*)d_out);
}